// round 16
// baseline (speedup 1.0000x reference)
#include <cuda_runtime.h>
#include <cuda_bf16.h>
#include <math.h>

#define SEQ 2048
#define HIDDIM 768
#define NQH 12
#define NKVH 3
#define HDIM 64
#define QKVC 1152        // (12 + 3 + 3) * 64
#define NEXP 16
#define FFD 1536
#define NROWS (SEQ * 2)  // top-2 assignments

// ---------------- bf16 mma helpers ----------------
__device__ __forceinline__ void mma_bf16(float* c, const unsigned* a, unsigned b0, unsigned b1) {
    asm("mma.sync.aligned.m16n8k16.row.col.f32.bf16.bf16.f32 "
        "{%0,%1,%2,%3}, {%4,%5,%6,%7}, {%8,%9}, {%0,%1,%2,%3};"
        : "+f"(c[0]), "+f"(c[1]), "+f"(c[2]), "+f"(c[3])
        : "r"(a[0]), "r"(a[1]), "r"(a[2]), "r"(a[3]), "r"(b0), "r"(b1));
}
// split a float pair into packed bf16x2 hi + lo (residual)
__device__ __forceinline__ void split_bf2(float x, float y, unsigned& hi, unsigned& lo) {
    __nv_bfloat162 h = __float22bfloat162_rn(make_float2(x, y));
    float2 hf = __bfloat1622float2(h);
    __nv_bfloat162 l = __float22bfloat162_rn(make_float2(x - hf.x, y - hf.y));
    hi = *(unsigned*)&h;
    lo = *(unsigned*)&l;
}

// ---------------- device-global scratch ----------------
__device__ float g_xn [SEQ * HIDDIM];
__device__ float g_qkv[SEQ * QKVC];
__device__ float g_att[SEQ * HIDDIM];
__device__ float g_h  [SEQ * HIDDIM];
__device__ float g_mi [SEQ * HIDDIM];
__device__ int   g_eidx[SEQ * 2];
__device__ float g_ew  [SEQ * 2];
__device__ int   g_cnt[NEXP];
__device__ int   g_off[NEXP + 1];
__device__ int   g_cur[NEXP];
__device__ int   g_rows_tok[NROWS];
__device__ float g_rows_w [NROWS];
__device__ int   g_tok_row[SEQ * 2];
__device__ float g_gu [(size_t)NROWS * 2 * FFD];  // 50 MB gate|up
__device__ float g_hid[(size_t)NROWS * FFD];      // 25 MB
__device__ float g_yex[(size_t)NROWS * HIDDIM];   // 12.6 MB
// split-K attention partials: 8 split q-tiles x 12 heads
__device__ float g_po[2][96][128 * 64];           // 6.3 MB
__device__ float g_pm[2][96][128];
__device__ float g_pl[2][96][128];

// ---------------- RMSNorm ----------------
__global__ void rmsnorm_kernel(const float* __restrict__ x, const float* __restrict__ w,
                               float* __restrict__ out) {
    int t = blockIdx.x;
    __shared__ float red[256];
    const float* xr = x + (size_t)t * HIDDIM;
    float ss = 0.f;
    for (int i = threadIdx.x; i < HIDDIM; i += 256) { float v = xr[i]; ss += v * v; }
    red[threadIdx.x] = ss;
    __syncthreads();
    for (int s2 = 128; s2 > 0; s2 >>= 1) {
        if (threadIdx.x < s2) red[threadIdx.x] += red[threadIdx.x + s2];
        __syncthreads();
    }
    float inv = rsqrtf(red[0] * (1.0f / HIDDIM) + 1e-6f);
    for (int i = threadIdx.x; i < HIDDIM; i += 256)
        out[(size_t)t * HIDDIM + i] = xr[i] * inv * w[i];
}

// ---------------- split-bf16 GEMM: CTA 128x128, k-chunk 64 (attention-proven layout) ----------------
// A smem: [128 rows][36] u32 k-pairs (Q-pattern, banks 4g+t)
// B smem: [32 k-pair-rows][136] u32 (V-pattern, banks 8t+g); memory B is [k][n] row-major
// MODE 0: C=A@B  1: +Res  2: moe1 gathered rows  3: moe2 scaled rows
template <int MODE>
__global__ __launch_bounds__(256, 2) void gemm_bf16(const float* __restrict__ A,
                                                    const float* __restrict__ B,
                                                    const float* __restrict__ Res,
                                                    float* __restrict__ C,
                                                    int M, int N, int K) {
    extern __shared__ unsigned dsm[];
    unsigned* Ah = dsm;                  // [128][36]
    unsigned* Al = Ah + 128 * 36;
    unsigned* Bh = Al + 128 * 36;        // [32][136]
    unsigned* Bl = Bh + 32 * 136;
    __shared__ int toks[128];

    int off = 0, cnt = M;
    const float* Bp = B;
    if (MODE >= 2) {
        int e = blockIdx.z;
        off = g_off[e];
        cnt = g_off[e + 1] - off;
        if ((int)blockIdx.y * 128 >= cnt) return;
        Bp = B + (size_t)e * K * N;
    }
    const int m0 = blockIdx.y * 128, n0 = blockIdx.x * 128;
    const int tid = threadIdx.x;

    if (MODE == 2) {
        if (tid < 128) {
            int rr = m0 + tid;
            toks[tid] = (rr < cnt) ? g_rows_tok[off + rr] : g_rows_tok[off];
        }
        __syncthreads();
    }

    const int wid = tid >> 5, lid = tid & 31;
    const int wm = (wid >> 1) * 32;   // 4 warps along M
    const int wn = (wid & 1) * 64;    // 2 warps along N
    const int g = lid >> 2, t = lid & 3;

    float acc[2][8][4];
#pragma unroll
    for (int mt = 0; mt < 2; mt++)
#pragma unroll
        for (int nt = 0; nt < 8; nt++)
#pragma unroll
            for (int i = 0; i < 4; i++) acc[mt][nt][i] = 0.f;

    const int NT = K >> 6;   // k-tiles of 64

    for (int kt = 0; kt < NT; ++kt) {
        const int k0 = kt * 64;

        // ---- producer: A tile [128][64] f32 -> hi/lo pairs along k ----
        for (int i = tid * 4; i < 128 * 64; i += 1024) {
            int m = i >> 6, d = i & 63;
            const float* ap;
            if (MODE == 2) ap = &A[(size_t)toks[m] * K + k0 + d];
            else if (MODE == 3) {
                int rr = m0 + m; if (rr >= cnt) rr = 0;
                ap = &A[(size_t)(off + rr) * K + k0 + d];
            } else ap = &A[(size_t)(m0 + m) * K + k0 + d];
            float4 v = *(const float4*)ap;
            unsigned hi, lo;
            split_bf2(v.x, v.y, hi, lo);
            Ah[m * 36 + (d >> 1)] = hi; Al[m * 36 + (d >> 1)] = lo;
            split_bf2(v.z, v.w, hi, lo);
            Ah[m * 36 + (d >> 1) + 1] = hi; Al[m * 36 + (d >> 1) + 1] = lo;
        }
        // ---- producer: B tile [64 k][128 n] -> pairs across adjacent k rows ----
        for (int it = tid; it < 1024; it += 256) {
            int pr = it >> 5, n4 = (it & 31) * 4;
            const float* wr = Bp + (size_t)(k0 + 2 * pr) * N + n0 + n4;
            float4 a = *(const float4*)wr;
            float4 b = *(const float4*)(wr + N);
            unsigned hi, lo;
            split_bf2(a.x, b.x, hi, lo); Bh[pr * 136 + n4 + 0] = hi; Bl[pr * 136 + n4 + 0] = lo;
            split_bf2(a.y, b.y, hi, lo); Bh[pr * 136 + n4 + 1] = hi; Bl[pr * 136 + n4 + 1] = lo;
            split_bf2(a.z, b.z, hi, lo); Bh[pr * 136 + n4 + 2] = hi; Bl[pr * 136 + n4 + 2] = lo;
            split_bf2(a.w, b.w, hi, lo); Bh[pr * 136 + n4 + 3] = hi; Bl[pr * 136 + n4 + 3] = lo;
        }
        __syncthreads();

        // ---- compute: 4 k16-steps ----
#pragma unroll
        for (int ksp = 0; ksp < 4; ksp++) {
            const int pb = ksp * 8;
            unsigned ah[2][4], al[2][4];
#pragma unroll
            for (int mt = 0; mt < 2; mt++) {
                const int rb = wm + mt * 16;
                ah[mt][0] = Ah[(rb + g) * 36 + pb + t];
                ah[mt][1] = Ah[(rb + g + 8) * 36 + pb + t];
                ah[mt][2] = Ah[(rb + g) * 36 + pb + t + 4];
                ah[mt][3] = Ah[(rb + g + 8) * 36 + pb + t + 4];
                al[mt][0] = Al[(rb + g) * 36 + pb + t];
                al[mt][1] = Al[(rb + g + 8) * 36 + pb + t];
                al[mt][2] = Al[(rb + g) * 36 + pb + t + 4];
                al[mt][3] = Al[(rb + g + 8) * 36 + pb + t + 4];
            }
#pragma unroll
            for (int nt = 0; nt < 8; nt++) {
                const int col = wn + nt * 8 + g;
                unsigned bh0 = Bh[(pb + t) * 136 + col];
                unsigned bh1 = Bh[(pb + t + 4) * 136 + col];
                unsigned bl0 = Bl[(pb + t) * 136 + col];
                unsigned bl1 = Bl[(pb + t + 4) * 136 + col];
                mma_bf16(acc[0][nt], ah[0], bh0, bh1);
                mma_bf16(acc[0][nt], ah[0], bl0, bl1);
                mma_bf16(acc[0][nt], al[0], bh0, bh1);
                mma_bf16(acc[1][nt], ah[1], bh0, bh1);
                mma_bf16(acc[1][nt], ah[1], bl0, bl1);
                mma_bf16(acc[1][nt], al[1], bh0, bh1);
            }
        }
        __syncthreads();
    }

    // ---- epilogue (same C-fragment mapping as before) ----
#pragma unroll
    for (int mt = 0; mt < 2; mt++) {
        const int lr0 = wm + mt * 16 + g;
        const int lr1 = lr0 + 8;
        if (MODE <= 1) {
            const size_t r0 = (size_t)(m0 + lr0) * N;
            const size_t r1 = (size_t)(m0 + lr1) * N;
#pragma unroll
            for (int nt = 0; nt < 8; nt++) {
                const int col = n0 + wn + nt * 8 + 2 * t;
                float2 v0 = make_float2(acc[mt][nt][0], acc[mt][nt][1]);
                float2 v1 = make_float2(acc[mt][nt][2], acc[mt][nt][3]);
                if (MODE == 1) {
                    float2 q0 = *(const float2*)&Res[r0 + col];
                    float2 q1 = *(const float2*)&Res[r1 + col];
                    v0.x += q0.x; v0.y += q0.y; v1.x += q1.x; v1.y += q1.y;
                }
                *(float2*)&C[r0 + col] = v0;
                *(float2*)&C[r1 + col] = v1;
            }
        } else {
            const int rr0 = m0 + lr0, rr1 = m0 + lr1;
            const bool s0 = rr0 < cnt, s1 = rr1 < cnt;
            float w0 = 1.f, w1 = 1.f;
            if (MODE == 3) {
                if (s0) w0 = g_rows_w[off + rr0];
                if (s1) w1 = g_rows_w[off + rr1];
            }
            const size_t r0 = (size_t)(off + rr0) * N;
            const size_t r1 = (size_t)(off + rr1) * N;
#pragma unroll
            for (int nt = 0; nt < 8; nt++) {
                const int col = n0 + wn + nt * 8 + 2 * t;
                if (s0) {
                    float2 v = make_float2(acc[mt][nt][0] * w0, acc[mt][nt][1] * w0);
                    *(float2*)&C[r0 + col] = v;
                }
                if (s1) {
                    float2 v = make_float2(acc[mt][nt][2] * w1, acc[mt][nt][3] * w1);
                    *(float2*)&C[r1 + col] = v;
                }
            }
        }
    }
}

// ---------------- SiLU(gate)*up from g_gu -> g_hid ----------------
__global__ void silu_kernel() {
    int i = blockIdx.x * blockDim.x + threadIdx.x;
    const int TOT = NROWS * (FFD / 4);
    if (i >= TOT) return;
    int r = i / (FFD / 4);
    int c4 = i % (FFD / 4);
    const float4* base = (const float4*)g_gu + (size_t)r * (2 * FFD / 4);
    float4 gv = base[c4];
    float4 uv = base[FFD / 4 + c4];
    float4 o;
    o.x = gv.x / (1.f + __expf(-gv.x)) * uv.x;
    o.y = gv.y / (1.f + __expf(-gv.y)) * uv.y;
    o.z = gv.z / (1.f + __expf(-gv.z)) * uv.z;
    o.w = gv.w / (1.f + __expf(-gv.w)) * uv.w;
    ((float4*)g_hid)[i] = o;
}

// ---------------- RoPE ----------------
__global__ void rope_kernel(float* __restrict__ qkv) {
    int s = blockIdx.x;
    int t = threadIdx.x;
    if (t >= (NQH + NKVH) * (HDIM / 2)) return;
    int hh = t / 32, p = t & 31;
    int col = (hh < NQH) ? hh * HDIM : (NQH * HDIM + (hh - NQH) * HDIM);
    float expo = (float)(2 * p) * (1.0f / HDIM);
    float inv = powf(10000.0f, -expo);
    float ang = (float)s * inv;
    float c, sn;
    sincosf(ang, &sn, &c);
    float* base = qkv + (size_t)s * QKVC + col;
    float x0 = base[2 * p], x1 = base[2 * p + 1];
    base[2 * p]     = x0 * c - x1 * sn;
    base[2 * p + 1] = x0 * sn + x1 * c;
}

// ---------------- causal flash attention, split-bf16 m16n8k16, static split-K ----------------
__global__ __launch_bounds__(256, 2) void attn_mma(const float* __restrict__ qkv,
                                                   float* __restrict__ out) {
    extern __shared__ unsigned smu[];
    unsigned* Qh = smu;               // [128][36]
    unsigned* Ql = Qh + 128 * 36;
    unsigned* Ph = Ql + 128 * 36;     // [128][36]
    unsigned* Pl = Ph + 128 * 36;
    unsigned* Kh = Pl + 128 * 36;     // [64][36]
    unsigned* Kl = Kh + 64 * 36;
    unsigned* Vh = Kl + 64 * 36;      // [32][72]
    unsigned* Vl = Vh + 32 * 72;

    const int h = blockIdx.y, kvh = h >> 2;
    const int w = blockIdx.x;
    int qtile, ktb, kte, seg;
    if (w < 8) { qtile = w; ktb = 0; kte = 2 * w + 1; seg = -1; }
    else {
        int j = w - 8;
        qtile = 8 + (j >> 1);
        seg = j & 1;
        ktb = seg ? (qtile + 1) : 0;
        kte = seg ? (2 * qtile + 1) : qtile;
    }
    const int q0 = qtile * 128;
    const int tid = threadIdx.x;
    const int wid = tid >> 5, lid = tid & 31;
    const int g = lid >> 2, t = lid & 3;
    const int wm = wid * 16;

    for (int i = tid * 4; i < 128 * 64; i += 1024) {
        int m = i >> 6, d = i & 63;
        float4 v = *(const float4*)&qkv[(size_t)(q0 + m) * QKVC + h * HDIM + d];
        unsigned hi, lo;
        split_bf2(v.x * 0.125f, v.y * 0.125f, hi, lo);
        Qh[m * 36 + (d >> 1)] = hi; Ql[m * 36 + (d >> 1)] = lo;
        split_bf2(v.z * 0.125f, v.w * 0.125f, hi, lo);
        Qh[m * 36 + (d >> 1) + 1] = hi; Ql[m * 36 + (d >> 1) + 1] = lo;
    }

    float rm0 = -1e30f, rm1 = -1e30f, rl0 = 0.f, rl1 = 0.f;
    float accO[8][4];
#pragma unroll
    for (int nt = 0; nt < 8; nt++)
#pragma unroll
        for (int i = 0; i < 4; i++) accO[nt][i] = 0.f;

    __syncthreads();

    for (int kt = ktb; kt <= kte; ++kt) {
        const int k0 = kt * 64;
        for (int i = tid * 4; i < 64 * 64; i += 1024) {
            int c = i >> 6, d = i & 63;
            float4 kv = *(const float4*)&qkv[(size_t)(k0 + c) * QKVC + NQH * HDIM + kvh * HDIM + d];
            unsigned hi, lo;
            split_bf2(kv.x, kv.y, hi, lo);
            Kh[c * 36 + (d >> 1)] = hi; Kl[c * 36 + (d >> 1)] = lo;
            split_bf2(kv.z, kv.w, hi, lo);
            Kh[c * 36 + (d >> 1) + 1] = hi; Kl[c * 36 + (d >> 1) + 1] = lo;
        }
        for (int i = tid * 4; i < 32 * 64; i += 1024) {
            int pr = i >> 6, d = i & 63;
            const float* r0p = &qkv[(size_t)(k0 + 2 * pr) * QKVC + (NQH + NKVH) * HDIM + kvh * HDIM + d];
            float4 v0 = *(const float4*)r0p;
            float4 v1 = *(const float4*)(r0p + QKVC);
            unsigned hi, lo;
            split_bf2(v0.x, v1.x, hi, lo); Vh[pr * 72 + d + 0] = hi; Vl[pr * 72 + d + 0] = lo;
            split_bf2(v0.y, v1.y, hi, lo); Vh[pr * 72 + d + 1] = hi; Vl[pr * 72 + d + 1] = lo;
            split_bf2(v0.z, v1.z, hi, lo); Vh[pr * 72 + d + 2] = hi; Vl[pr * 72 + d + 2] = lo;
            split_bf2(v0.w, v1.w, hi, lo); Vh[pr * 72 + d + 3] = hi; Vl[pr * 72 + d + 3] = lo;
        }
        __syncthreads();

        float s[8][4];
#pragma unroll
        for (int nt = 0; nt < 8; nt++)
#pragma unroll
            for (int i = 0; i < 4; i++) s[nt][i] = 0.f;
#pragma unroll
        for (int ksp = 0; ksp < 4; ksp++) {
            const int pb = ksp * 8;
            unsigned ah[4], al[4];
            ah[0] = Qh[(wm + g) * 36 + pb + t];
            ah[1] = Qh[(wm + g + 8) * 36 + pb + t];
            ah[2] = Qh[(wm + g) * 36 + pb + t + 4];
            ah[3] = Qh[(wm + g + 8) * 36 + pb + t + 4];
            al[0] = Ql[(wm + g) * 36 + pb + t];
            al[1] = Ql[(wm + g + 8) * 36 + pb + t];
            al[2] = Ql[(wm + g) * 36 + pb + t + 4];
            al[3] = Ql[(wm + g + 8) * 36 + pb + t + 4];
#pragma unroll
            for (int nt = 0; nt < 8; nt++) {
                unsigned bh0 = Kh[(nt * 8 + g) * 36 + pb + t];
                unsigned bh1 = Kh[(nt * 8 + g) * 36 + pb + t + 4];
                unsigned bl0 = Kl[(nt * 8 + g) * 36 + pb + t];
                unsigned bl1 = Kl[(nt * 8 + g) * 36 + pb + t + 4];
                mma_bf16(s[nt], ah, bh0, bh1);
                mma_bf16(s[nt], ah, bl0, bl1);
                mma_bf16(s[nt], al, bh0, bh1);
            }
        }

        if (k0 + 63 > q0 + wm) {
            const int row0 = q0 + wm + g, row1 = row0 + 8;
#pragma unroll
            for (int nt = 0; nt < 8; nt++) {
                int c0 = k0 + nt * 8 + 2 * t, c1 = c0 + 1;
                if (c0 > row0) s[nt][0] = -1e30f;
                if (c1 > row0) s[nt][1] = -1e30f;
                if (c0 > row1) s[nt][2] = -1e30f;
                if (c1 > row1) s[nt][3] = -1e30f;
            }
        }

        float m0 = -1e30f, m1 = -1e30f;
#pragma unroll
        for (int nt = 0; nt < 8; nt++) {
            m0 = fmaxf(m0, fmaxf(s[nt][0], s[nt][1]));
            m1 = fmaxf(m1, fmaxf(s[nt][2], s[nt][3]));
        }
        m0 = fmaxf(m0, __shfl_xor_sync(0xffffffffu, m0, 1));
        m0 = fmaxf(m0, __shfl_xor_sync(0xffffffffu, m0, 2));
        m1 = fmaxf(m1, __shfl_xor_sync(0xffffffffu, m1, 1));
        m1 = fmaxf(m1, __shfl_xor_sync(0xffffffffu, m1, 2));
        float nm0 = fmaxf(rm0, m0), nm1 = fmaxf(rm1, m1);
        float al0 = __expf(rm0 - nm0), al1 = __expf(rm1 - nm1);
        rm0 = nm0; rm1 = nm1;

        float ls0 = 0.f, ls1 = 0.f;
#pragma unroll
        for (int nt = 0; nt < 8; nt++) {
            float p00 = __expf(s[nt][0] - nm0);
            float p01 = __expf(s[nt][1] - nm0);
            float p10 = __expf(s[nt][2] - nm1);
            float p11 = __expf(s[nt][3] - nm1);
            ls0 += p00 + p01;
            ls1 += p10 + p11;
            unsigned hi, lo;
            split_bf2(p00, p01, hi, lo);
            Ph[(wm + g) * 36 + 4 * nt + t] = hi;
            Pl[(wm + g) * 36 + 4 * nt + t] = lo;
            split_bf2(p10, p11, hi, lo);
            Ph[(wm + g + 8) * 36 + 4 * nt + t] = hi;
            Pl[(wm + g + 8) * 36 + 4 * nt + t] = lo;
        }
        ls0 += __shfl_xor_sync(0xffffffffu, ls0, 1);
        ls0 += __shfl_xor_sync(0xffffffffu, ls0, 2);
        ls1 += __shfl_xor_sync(0xffffffffu, ls1, 1);
        ls1 += __shfl_xor_sync(0xffffffffu, ls1, 2);
        rl0 = rl0 * al0 + ls0;
        rl1 = rl1 * al1 + ls1;

#pragma unroll
        for (int nt = 0; nt < 8; nt++) {
            accO[nt][0] *= al0; accO[nt][1] *= al0;
            accO[nt][2] *= al1; accO[nt][3] *= al1;
        }
        __syncwarp();

#pragma unroll
        for (int ksp = 0; ksp < 4; ksp++) {
            const int pb = ksp * 8;
            unsigned ah[4], al[4];
            ah[0] = Ph[(wm + g) * 36 + pb + t];
            ah[1] = Ph[(wm + g + 8) * 36 + pb + t];
            ah[2] = Ph[(wm + g) * 36 + pb + t + 4];
            ah[3] = Ph[(wm + g + 8) * 36 + pb + t + 4];
            al[0] = Pl[(wm + g) * 36 + pb + t];
            al[1] = Pl[(wm + g + 8) * 36 + pb + t];
            al[2] = Pl[(wm + g) * 36 + pb + t + 4];
            al[3] = Pl[(wm + g + 8) * 36 + pb + t + 4];
#pragma unroll
            for (int nt = 0; nt < 8; nt++) {
                unsigned bh0 = Vh[(pb + t) * 72 + nt * 8 + g];
                unsigned bh1 = Vh[(pb + t + 4) * 72 + nt * 8 + g];
                unsigned bl0 = Vl[(pb + t) * 72 + nt * 8 + g];
                unsigned bl1 = Vl[(pb + t + 4) * 72 + nt * 8 + g];
                mma_bf16(accO[nt], ah, bh0, bh1);
                mma_bf16(accO[nt], ah, bl0, bl1);
                mma_bf16(accO[nt], al, bh0, bh1);
            }
        }
        __syncthreads();
    }

    const int lrow0 = wm + g, lrow1 = lrow0 + 8;
    if (seg < 0) {
        float inv0 = 1.f / rl0, inv1 = 1.f / rl1;
        const int row0 = q0 + lrow0, row1 = q0 + lrow1;
#pragma unroll
        for (int nt = 0; nt < 8; nt++) {
            const int col = h * HDIM + nt * 8 + 2 * t;
            *(float2*)&out[(size_t)row0 * (NQH * HDIM) + col] =
                make_float2(accO[nt][0] * inv0, accO[nt][1] * inv0);
            *(float2*)&out[(size_t)row1 * (NQH * HDIM) + col] =
                make_float2(accO[nt][2] * inv1, accO[nt][3] * inv1);
        }
    } else {
        const int pi = (qtile - 8) * NQH + h;
        float* po = g_po[seg][pi];
#pragma unroll
        for (int nt = 0; nt < 8; nt++) {
            const int col = nt * 8 + 2 * t;
            *(float2*)&po[lrow0 * 64 + col] = make_float2(accO[nt][0], accO[nt][1]);
            *(float2*)&po[lrow1 * 64 + col] = make_float2(accO[nt][2], accO[nt][3]);
        }
        if (t == 0) {
            g_pm[seg][pi][lrow0] = rm0;
            g_pl[seg][pi][lrow0] = rl0;
            g_pm[seg][pi][lrow1] = rm1;
            g_pl[seg][pi][lrow1] = rl1;
        }
    }
}

// ---------------- split-K combine ----------------
__global__ void attn_combine(float* __restrict__ out) {
    const int pi = blockIdx.x;              // 0..95
    const int qtile = 8 + pi / NQH, h = pi % NQH;
    const int row = threadIdx.x >> 1;       // 0..127
    const int ch = (threadIdx.x & 1) * 32;  // column half
    float m0 = g_pm[0][pi][row], m1 = g_pm[1][pi][row];
    float l0 = g_pl[0][pi][row], l1 = g_pl[1][pi][row];
    float m = fmaxf(m0, m1);
    float a0 = __expf(m0 - m), a1 = __expf(m1 - m);
    float inv = 1.f / (l0 * a0 + l1 * a1);
    a0 *= inv; a1 *= inv;
    const float* O0 = &g_po[0][pi][row * 64 + ch];
    const float* O1 = &g_po[1][pi][row * 64 + ch];
    float* dst = &out[(size_t)(qtile * 128 + row) * (NQH * HDIM) + h * HDIM + ch];
#pragma unroll
    for (int c = 0; c < 32; c += 4) {
        float4 x0 = *(const float4*)(O0 + c);
        float4 x1 = *(const float4*)(O1 + c);
        float4 o;
        o.x = x0.x * a0 + x1.x * a1;
        o.y = x0.y * a0 + x1.y * a1;
        o.z = x0.z * a0 + x1.z * a1;
        o.w = x0.w * a0 + x1.w * a1;
        *(float4*)(dst + c) = o;
    }
}

// ---------------- router ----------------
__global__ void router_kernel(const float* __restrict__ x, const float* __restrict__ wr) {
    int t = blockIdx.x;
    __shared__ float xr[HIDDIM];
    __shared__ float lg[NEXP];
    for (int i = threadIdx.x; i < HIDDIM; i += blockDim.x) xr[i] = x[(size_t)t * HIDDIM + i];
    __syncthreads();
    if (threadIdx.x < NEXP) {
        float a = 0.f;
        for (int k = 0; k < HIDDIM; k++) a += xr[k] * wr[k * NEXP + threadIdx.x];
        lg[threadIdx.x] = a;
    }
    __syncthreads();
    if (threadIdx.x == 0) {
        int i0 = 0; float l0 = lg[0];
        for (int e = 1; e < NEXP; e++) if (lg[e] > l0) { l0 = lg[e]; i0 = e; }
        int i1 = (i0 == 0) ? 1 : 0; float l1 = lg[i1];
        for (int e = 0; e < NEXP; e++) if (e != i0 && lg[e] > l1) { l1 = lg[e]; i1 = e; }
        float w0 = 1.f / (1.f + __expf(l1 - l0));
        g_eidx[2 * t] = i0; g_eidx[2 * t + 1] = i1;
        g_ew[2 * t] = w0;   g_ew[2 * t + 1] = 1.f - w0;
        atomicAdd(&g_cnt[i0], 1);
        atomicAdd(&g_cnt[i1], 1);
    }
}

__global__ void zero_cnt_kernel() { if (threadIdx.x < NEXP) g_cnt[threadIdx.x] = 0; }

__global__ void prefix_kernel() {
    if (threadIdx.x == 0) {
        int acc = 0;
        for (int e = 0; e < NEXP; e++) { g_off[e] = acc; g_cur[e] = acc; acc += g_cnt[e]; }
        g_off[NEXP] = acc;
    }
}

__global__ void scatter_kernel() {
    int t = blockIdx.x * blockDim.x + threadIdx.x;
    if (t >= SEQ) return;
    for (int j = 0; j < 2; j++) {
        int e = g_eidx[2 * t + j];
        int pos = atomicAdd(&g_cur[e], 1);
        g_rows_tok[pos] = t;
        g_rows_w[pos] = g_ew[2 * t + j];
        g_tok_row[2 * t + j] = pos;
    }
}

// ---------------- final combine ----------------
__global__ void combine_kernel(float* __restrict__ out) {
    int t = blockIdx.x;
    int r0 = g_tok_row[2 * t], r1 = g_tok_row[2 * t + 1];
    const float* hr = g_h + (size_t)t * HIDDIM;
    const float* y0 = g_yex + (size_t)r0 * HIDDIM;
    const float* y1 = g_yex + (size_t)r1 * HIDDIM;
    for (int d = threadIdx.x; d < HIDDIM; d += blockDim.x)
        out[(size_t)t * HIDDIM + d] = hr[d] + y0[d] + y1[d];
}

// ---------------- launch ----------------
extern "C" void kernel_launch(void* const* d_in, const int* in_sizes, int n_in,
                              void* d_out, int out_size) {
    const float* x    = (const float*)d_in[0];
    const float* n1w  = (const float*)d_in[1];
    const float* wqkv = (const float*)d_in[2];
    const float* wout = (const float*)d_in[3];
    const float* n2w  = (const float*)d_in[4];
    const float* wr   = (const float*)d_in[5];
    const float* wgu  = (const float*)d_in[6];
    const float* wd   = (const float*)d_in[7];
    float* out = (float*)d_out;

    void *p_xn, *p_qkv, *p_att, *p_h, *p_mi, *p_gu, *p_hid, *p_yex;
    cudaGetSymbolAddress(&p_xn, g_xn);
    cudaGetSymbolAddress(&p_qkv, g_qkv);
    cudaGetSymbolAddress(&p_att, g_att);
    cudaGetSymbolAddress(&p_h, g_h);
    cudaGetSymbolAddress(&p_mi, g_mi);
    cudaGetSymbolAddress(&p_gu, g_gu);
    cudaGetSymbolAddress(&p_hid, g_hid);
    cudaGetSymbolAddress(&p_yex, g_yex);

    const int smem_gemm = (2 * 128 * 36 + 2 * 32 * 136) * 4;   // 71680 B
    cudaFuncSetAttribute(gemm_bf16<0>, cudaFuncAttributeMaxDynamicSharedMemorySize, smem_gemm);
    cudaFuncSetAttribute(gemm_bf16<1>, cudaFuncAttributeMaxDynamicSharedMemorySize, smem_gemm);
    cudaFuncSetAttribute(gemm_bf16<2>, cudaFuncAttributeMaxDynamicSharedMemorySize, smem_gemm);
    cudaFuncSetAttribute(gemm_bf16<3>, cudaFuncAttributeMaxDynamicSharedMemorySize, smem_gemm);

    // 1. pre-attention RMSNorm
    rmsnorm_kernel<<<SEQ, 256>>>(x, n1w, (float*)p_xn);

    // 2. QKV projection (split-bf16 mma)
    {
        dim3 grid(QKVC / 128, SEQ / 128);
        gemm_bf16<0><<<grid, 256, smem_gemm>>>((const float*)p_xn, wqkv, nullptr, (float*)p_qkv,
                                               SEQ, QKVC, HIDDIM);
    }

    // 3. RoPE
    rope_kernel<<<SEQ, 512>>>((float*)p_qkv);

    // 4. causal flash attention (split-bf16 mma, static split-K balancing)
    {
        dim3 grid(24, NQH);
        size_t smem = (size_t)(4 * 128 * 36 + 2 * 64 * 36 + 2 * 32 * 72) * sizeof(unsigned);
        cudaFuncSetAttribute(attn_mma, cudaFuncAttributeMaxDynamicSharedMemorySize, (int)smem);
        attn_mma<<<grid, 256, smem>>>((const float*)p_qkv, (float*)p_att);
        attn_combine<<<96, 256>>>((float*)p_att);
    }

    // 5. output projection + residual (split-bf16 mma)
    {
        dim3 grid(HIDDIM / 128, SEQ / 128);
        gemm_bf16<1><<<grid, 256, smem_gemm>>>((const float*)p_att, wout, x, (float*)p_h,
                                               SEQ, HIDDIM, NQH * HDIM);
    }

    // 6. pre-MoE RMSNorm
    rmsnorm_kernel<<<SEQ, 256>>>((const float*)p_h, n2w, (float*)p_mi);

    // 7. routing
    zero_cnt_kernel<<<1, 32>>>();
    router_kernel<<<SEQ, 128>>>((const float*)p_mi, wr);
    prefix_kernel<<<1, 1>>>();
    scatter_kernel<<<(SEQ + 255) / 256, 256>>>();

    // 8. expert gate/up GEMM -> g_gu (split-bf16, gathered rows)
    {
        dim3 grid((2 * FFD) / 128, NROWS / 128, NEXP);
        gemm_bf16<2><<<grid, 256, smem_gemm>>>((const float*)p_mi, wgu, nullptr, (float*)p_gu,
                                               NROWS, 2 * FFD, HIDDIM);
    }

    // 8b. SiLU(gate) * up -> g_hid
    {
        int tot = NROWS * (FFD / 4);
        silu_kernel<<<(tot + 255) / 256, 256>>>();
    }

    // 9. expert down GEMM -> g_yex (split-bf16, combine-weight scaled)
    {
        dim3 grid(HIDDIM / 128, NROWS / 128, NEXP);
        gemm_bf16<3><<<grid, 256, smem_gemm>>>((const float*)p_hid, wd, nullptr, (float*)p_yex,
                                               NROWS, HIDDIM, FFD);
    }

    // 10. combine
    combine_kernel<<<SEQ, 256>>>(out);
}

// round 17
// speedup vs baseline: 1.2685x; 1.2685x over previous
#include <cuda_runtime.h>
#include <cuda_bf16.h>
#include <cuda_fp16.h>
#include <math.h>

#define SEQ 2048
#define HIDDIM 768
#define NQH 12
#define NKVH 3
#define HDIM 64
#define QKVC 1152        // (12 + 3 + 3) * 64
#define NEXP 16
#define FFD 1536
#define NROWS (SEQ * 2)  // top-2 assignments

// ---------------- fp16 mma helpers (GEMMs) ----------------
__device__ __forceinline__ void mma_fp16(float* c, const unsigned* a, unsigned b0, unsigned b1) {
    asm("mma.sync.aligned.m16n8k16.row.col.f32.f16.f16.f32 "
        "{%0,%1,%2,%3}, {%4,%5,%6,%7}, {%8,%9}, {%0,%1,%2,%3};"
        : "+f"(c[0]), "+f"(c[1]), "+f"(c[2]), "+f"(c[3])
        : "r"(a[0]), "r"(a[1]), "r"(a[2]), "r"(a[3]), "r"(b0), "r"(b1));
}
__device__ __forceinline__ unsigned f2h2(float x, float y) {
    __half2 h = __float22half2_rn(make_float2(x, y));
    return *(unsigned*)&h;
}
// ---------------- bf16 mma helpers (attention) ----------------
__device__ __forceinline__ void mma_bf16(float* c, const unsigned* a, unsigned b0, unsigned b1) {
    asm("mma.sync.aligned.m16n8k16.row.col.f32.bf16.bf16.f32 "
        "{%0,%1,%2,%3}, {%4,%5,%6,%7}, {%8,%9}, {%0,%1,%2,%3};"
        : "+f"(c[0]), "+f"(c[1]), "+f"(c[2]), "+f"(c[3])
        : "r"(a[0]), "r"(a[1]), "r"(a[2]), "r"(a[3]), "r"(b0), "r"(b1));
}
// split a float pair into packed bf16x2 hi + lo (residual)
__device__ __forceinline__ void split_bf2(float x, float y, unsigned& hi, unsigned& lo) {
    __nv_bfloat162 h = __float22bfloat162_rn(make_float2(x, y));
    float2 hf = __bfloat1622float2(h);
    __nv_bfloat162 l = __float22bfloat162_rn(make_float2(x - hf.x, y - hf.y));
    hi = *(unsigned*)&h;
    lo = *(unsigned*)&l;
}

// ---------------- device-global scratch ----------------
__device__ float g_xn [SEQ * HIDDIM];
__device__ float g_qkv[SEQ * QKVC];
__device__ float g_att[SEQ * HIDDIM];
__device__ float g_h  [SEQ * HIDDIM];
__device__ float g_mi [SEQ * HIDDIM];
__device__ int   g_eidx[SEQ * 2];
__device__ float g_ew  [SEQ * 2];
__device__ int   g_cnt[NEXP];
__device__ int   g_off[NEXP + 1];
__device__ int   g_cur[NEXP];
__device__ int   g_rows_tok[NROWS];
__device__ float g_rows_w [NROWS];
__device__ int   g_tok_row[SEQ * 2];
__device__ float g_gu [(size_t)NROWS * 2 * FFD];  // 50 MB gate|up
__device__ float g_hid[(size_t)NROWS * FFD];      // 25 MB
__device__ float g_yex[(size_t)NROWS * HIDDIM];   // 12.6 MB
// split-K attention partials: 8 split q-tiles x 12 heads
__device__ float g_po[2][96][128 * 64];           // 6.3 MB
__device__ float g_pm[2][96][128];
__device__ float g_pl[2][96][128];

// ---------------- RMSNorm ----------------
__global__ void rmsnorm_kernel(const float* __restrict__ x, const float* __restrict__ w,
                               float* __restrict__ out) {
    int t = blockIdx.x;
    __shared__ float red[256];
    const float* xr = x + (size_t)t * HIDDIM;
    float ss = 0.f;
    for (int i = threadIdx.x; i < HIDDIM; i += 256) { float v = xr[i]; ss += v * v; }
    red[threadIdx.x] = ss;
    __syncthreads();
    for (int s2 = 128; s2 > 0; s2 >>= 1) {
        if (threadIdx.x < s2) red[threadIdx.x] += red[threadIdx.x + s2];
        __syncthreads();
    }
    float inv = rsqrtf(red[0] * (1.0f / HIDDIM) + 1e-6f);
    for (int i = threadIdx.x; i < HIDDIM; i += 256)
        out[(size_t)t * HIDDIM + i] = xr[i] * inv * w[i];
}

// ---------------- fp16 GEMM: CTA 128x128, k-chunk 64 ----------------
// A smem: [128 rows][36] u32 fp16x2 k-pairs (banks 4g+t)
// B smem: [32 k-pair-rows][136] u32 fp16x2 (banks 8t+g); memory B is [k][n] row-major
// MODE 0: C=A@B  1: +Res  2: moe1 gathered rows  3: moe2 scaled rows
template <int MODE>
__global__ __launch_bounds__(256, 2) void gemm_fp16(const float* __restrict__ A,
                                                    const float* __restrict__ B,
                                                    const float* __restrict__ Res,
                                                    float* __restrict__ C,
                                                    int M, int N, int K) {
    extern __shared__ unsigned dsm[];
    unsigned* Ah = dsm;                  // [128][36]
    unsigned* Bh = Ah + 128 * 36;        // [32][136]
    __shared__ int toks[128];

    int off = 0, cnt = M;
    const float* Bp = B;
    if (MODE >= 2) {
        int e = blockIdx.z;
        off = g_off[e];
        cnt = g_off[e + 1] - off;
        if ((int)blockIdx.y * 128 >= cnt) return;
        Bp = B + (size_t)e * K * N;
    }
    const int m0 = blockIdx.y * 128, n0 = blockIdx.x * 128;
    const int tid = threadIdx.x;

    if (MODE == 2) {
        if (tid < 128) {
            int rr = m0 + tid;
            toks[tid] = (rr < cnt) ? g_rows_tok[off + rr] : g_rows_tok[off];
        }
        __syncthreads();
    }

    const int wid = tid >> 5, lid = tid & 31;
    const int wm = (wid >> 1) * 32;   // 4 warps along M
    const int wn = (wid & 1) * 64;    // 2 warps along N
    const int g = lid >> 2, t = lid & 3;

    float acc[2][8][4];
#pragma unroll
    for (int mt = 0; mt < 2; mt++)
#pragma unroll
        for (int nt = 0; nt < 8; nt++)
#pragma unroll
            for (int i = 0; i < 4; i++) acc[mt][nt][i] = 0.f;

    const int NT = K >> 6;   // k-tiles of 64

    for (int kt = 0; kt < NT; ++kt) {
        const int k0 = kt * 64;

        // ---- producer: A tile [128][64] f32 -> fp16x2 pairs along k ----
        for (int i = tid * 4; i < 128 * 64; i += 1024) {
            int m = i >> 6, d = i & 63;
            const float* ap;
            if (MODE == 2) ap = &A[(size_t)toks[m] * K + k0 + d];
            else if (MODE == 3) {
                int rr = m0 + m; if (rr >= cnt) rr = 0;
                ap = &A[(size_t)(off + rr) * K + k0 + d];
            } else ap = &A[(size_t)(m0 + m) * K + k0 + d];
            float4 v = *(const float4*)ap;
            Ah[m * 36 + (d >> 1)]     = f2h2(v.x, v.y);
            Ah[m * 36 + (d >> 1) + 1] = f2h2(v.z, v.w);
        }
        // ---- producer: B tile [64 k][128 n] -> fp16x2 pairs across adjacent k rows ----
        for (int it = tid; it < 1024; it += 256) {
            int pr = it >> 5, n4 = (it & 31) * 4;
            const float* wr = Bp + (size_t)(k0 + 2 * pr) * N + n0 + n4;
            float4 a = *(const float4*)wr;
            float4 b = *(const float4*)(wr + N);
            Bh[pr * 136 + n4 + 0] = f2h2(a.x, b.x);
            Bh[pr * 136 + n4 + 1] = f2h2(a.y, b.y);
            Bh[pr * 136 + n4 + 2] = f2h2(a.z, b.z);
            Bh[pr * 136 + n4 + 3] = f2h2(a.w, b.w);
        }
        __syncthreads();

        // ---- compute: 4 k16-steps, 1 fp16 mma each ----
#pragma unroll
        for (int ksp = 0; ksp < 4; ksp++) {
            const int pb = ksp * 8;
            unsigned a[2][4];
#pragma unroll
            for (int mt = 0; mt < 2; mt++) {
                const int rb = wm + mt * 16;
                a[mt][0] = Ah[(rb + g) * 36 + pb + t];
                a[mt][1] = Ah[(rb + g + 8) * 36 + pb + t];
                a[mt][2] = Ah[(rb + g) * 36 + pb + t + 4];
                a[mt][3] = Ah[(rb + g + 8) * 36 + pb + t + 4];
            }
#pragma unroll
            for (int nt = 0; nt < 8; nt++) {
                const int col = wn + nt * 8 + g;
                unsigned b0 = Bh[(pb + t) * 136 + col];
                unsigned b1 = Bh[(pb + t + 4) * 136 + col];
                mma_fp16(acc[0][nt], a[0], b0, b1);
                mma_fp16(acc[1][nt], a[1], b0, b1);
            }
        }
        __syncthreads();
    }

    // ---- epilogue ----
#pragma unroll
    for (int mt = 0; mt < 2; mt++) {
        const int lr0 = wm + mt * 16 + g;
        const int lr1 = lr0 + 8;
        if (MODE <= 1) {
            const size_t r0 = (size_t)(m0 + lr0) * N;
            const size_t r1 = (size_t)(m0 + lr1) * N;
#pragma unroll
            for (int nt = 0; nt < 8; nt++) {
                const int col = n0 + wn + nt * 8 + 2 * t;
                float2 v0 = make_float2(acc[mt][nt][0], acc[mt][nt][1]);
                float2 v1 = make_float2(acc[mt][nt][2], acc[mt][nt][3]);
                if (MODE == 1) {
                    float2 q0 = *(const float2*)&Res[r0 + col];
                    float2 q1 = *(const float2*)&Res[r1 + col];
                    v0.x += q0.x; v0.y += q0.y; v1.x += q1.x; v1.y += q1.y;
                }
                *(float2*)&C[r0 + col] = v0;
                *(float2*)&C[r1 + col] = v1;
            }
        } else {
            const int rr0 = m0 + lr0, rr1 = m0 + lr1;
            const bool s0 = rr0 < cnt, s1 = rr1 < cnt;
            float w0 = 1.f, w1 = 1.f;
            if (MODE == 3) {
                if (s0) w0 = g_rows_w[off + rr0];
                if (s1) w1 = g_rows_w[off + rr1];
            }
            const size_t r0 = (size_t)(off + rr0) * N;
            const size_t r1 = (size_t)(off + rr1) * N;
#pragma unroll
            for (int nt = 0; nt < 8; nt++) {
                const int col = n0 + wn + nt * 8 + 2 * t;
                if (s0) {
                    float2 v = make_float2(acc[mt][nt][0] * w0, acc[mt][nt][1] * w0);
                    *(float2*)&C[r0 + col] = v;
                }
                if (s1) {
                    float2 v = make_float2(acc[mt][nt][2] * w1, acc[mt][nt][3] * w1);
                    *(float2*)&C[r1 + col] = v;
                }
            }
        }
    }
}

// ---------------- SiLU(gate)*up from g_gu -> g_hid ----------------
__global__ void silu_kernel() {
    int i = blockIdx.x * blockDim.x + threadIdx.x;
    const int TOT = NROWS * (FFD / 4);
    if (i >= TOT) return;
    int r = i / (FFD / 4);
    int c4 = i % (FFD / 4);
    const float4* base = (const float4*)g_gu + (size_t)r * (2 * FFD / 4);
    float4 gv = base[c4];
    float4 uv = base[FFD / 4 + c4];
    float4 o;
    o.x = gv.x / (1.f + __expf(-gv.x)) * uv.x;
    o.y = gv.y / (1.f + __expf(-gv.y)) * uv.y;
    o.z = gv.z / (1.f + __expf(-gv.z)) * uv.z;
    o.w = gv.w / (1.f + __expf(-gv.w)) * uv.w;
    ((float4*)g_hid)[i] = o;
}

// ---------------- RoPE ----------------
__global__ void rope_kernel(float* __restrict__ qkv) {
    int s = blockIdx.x;
    int t = threadIdx.x;
    if (t >= (NQH + NKVH) * (HDIM / 2)) return;
    int hh = t / 32, p = t & 31;
    int col = (hh < NQH) ? hh * HDIM : (NQH * HDIM + (hh - NQH) * HDIM);
    float expo = (float)(2 * p) * (1.0f / HDIM);
    float inv = powf(10000.0f, -expo);
    float ang = (float)s * inv;
    float c, sn;
    sincosf(ang, &sn, &c);
    float* base = qkv + (size_t)s * QKVC + col;
    float x0 = base[2 * p], x1 = base[2 * p + 1];
    base[2 * p]     = x0 * c - x1 * sn;
    base[2 * p + 1] = x0 * sn + x1 * c;
}

// ---------------- causal flash attention, split-bf16 m16n8k16, static split-K ----------------
__global__ __launch_bounds__(256, 2) void attn_mma(const float* __restrict__ qkv,
                                                   float* __restrict__ out) {
    extern __shared__ unsigned smu[];
    unsigned* Qh = smu;               // [128][36]
    unsigned* Ql = Qh + 128 * 36;
    unsigned* Ph = Ql + 128 * 36;     // [128][36]
    unsigned* Pl = Ph + 128 * 36;
    unsigned* Kh = Pl + 128 * 36;     // [64][36]
    unsigned* Kl = Kh + 64 * 36;
    unsigned* Vh = Kl + 64 * 36;      // [32][72]
    unsigned* Vl = Vh + 32 * 72;

    const int h = blockIdx.y, kvh = h >> 2;
    const int w = blockIdx.x;
    int qtile, ktb, kte, seg;
    if (w < 8) { qtile = w; ktb = 0; kte = 2 * w + 1; seg = -1; }
    else {
        int j = w - 8;
        qtile = 8 + (j >> 1);
        seg = j & 1;
        ktb = seg ? (qtile + 1) : 0;
        kte = seg ? (2 * qtile + 1) : qtile;
    }
    const int q0 = qtile * 128;
    const int tid = threadIdx.x;
    const int wid = tid >> 5, lid = tid & 31;
    const int g = lid >> 2, t = lid & 3;
    const int wm = wid * 16;

    for (int i = tid * 4; i < 128 * 64; i += 1024) {
        int m = i >> 6, d = i & 63;
        float4 v = *(const float4*)&qkv[(size_t)(q0 + m) * QKVC + h * HDIM + d];
        unsigned hi, lo;
        split_bf2(v.x * 0.125f, v.y * 0.125f, hi, lo);
        Qh[m * 36 + (d >> 1)] = hi; Ql[m * 36 + (d >> 1)] = lo;
        split_bf2(v.z * 0.125f, v.w * 0.125f, hi, lo);
        Qh[m * 36 + (d >> 1) + 1] = hi; Ql[m * 36 + (d >> 1) + 1] = lo;
    }

    float rm0 = -1e30f, rm1 = -1e30f, rl0 = 0.f, rl1 = 0.f;
    float accO[8][4];
#pragma unroll
    for (int nt = 0; nt < 8; nt++)
#pragma unroll
        for (int i = 0; i < 4; i++) accO[nt][i] = 0.f;

    __syncthreads();

    for (int kt = ktb; kt <= kte; ++kt) {
        const int k0 = kt * 64;
        for (int i = tid * 4; i < 64 * 64; i += 1024) {
            int c = i >> 6, d = i & 63;
            float4 kv = *(const float4*)&qkv[(size_t)(k0 + c) * QKVC + NQH * HDIM + kvh * HDIM + d];
            unsigned hi, lo;
            split_bf2(kv.x, kv.y, hi, lo);
            Kh[c * 36 + (d >> 1)] = hi; Kl[c * 36 + (d >> 1)] = lo;
            split_bf2(kv.z, kv.w, hi, lo);
            Kh[c * 36 + (d >> 1) + 1] = hi; Kl[c * 36 + (d >> 1) + 1] = lo;
        }
        for (int i = tid * 4; i < 32 * 64; i += 1024) {
            int pr = i >> 6, d = i & 63;
            const float* r0p = &qkv[(size_t)(k0 + 2 * pr) * QKVC + (NQH + NKVH) * HDIM + kvh * HDIM + d];
            float4 v0 = *(const float4*)r0p;
            float4 v1 = *(const float4*)(r0p + QKVC);
            unsigned hi, lo;
            split_bf2(v0.x, v1.x, hi, lo); Vh[pr * 72 + d + 0] = hi; Vl[pr * 72 + d + 0] = lo;
            split_bf2(v0.y, v1.y, hi, lo); Vh[pr * 72 + d + 1] = hi; Vl[pr * 72 + d + 1] = lo;
            split_bf2(v0.z, v1.z, hi, lo); Vh[pr * 72 + d + 2] = hi; Vl[pr * 72 + d + 2] = lo;
            split_bf2(v0.w, v1.w, hi, lo); Vh[pr * 72 + d + 3] = hi; Vl[pr * 72 + d + 3] = lo;
        }
        __syncthreads();

        float s[8][4];
#pragma unroll
        for (int nt = 0; nt < 8; nt++)
#pragma unroll
            for (int i = 0; i < 4; i++) s[nt][i] = 0.f;
#pragma unroll
        for (int ksp = 0; ksp < 4; ksp++) {
            const int pb = ksp * 8;
            unsigned ah[4], al[4];
            ah[0] = Qh[(wm + g) * 36 + pb + t];
            ah[1] = Qh[(wm + g + 8) * 36 + pb + t];
            ah[2] = Qh[(wm + g) * 36 + pb + t + 4];
            ah[3] = Qh[(wm + g + 8) * 36 + pb + t + 4];
            al[0] = Ql[(wm + g) * 36 + pb + t];
            al[1] = Ql[(wm + g + 8) * 36 + pb + t];
            al[2] = Ql[(wm + g) * 36 + pb + t + 4];
            al[3] = Ql[(wm + g + 8) * 36 + pb + t + 4];
#pragma unroll
            for (int nt = 0; nt < 8; nt++) {
                unsigned bh0 = Kh[(nt * 8 + g) * 36 + pb + t];
                unsigned bh1 = Kh[(nt * 8 + g) * 36 + pb + t + 4];
                unsigned bl0 = Kl[(nt * 8 + g) * 36 + pb + t];
                unsigned bl1 = Kl[(nt * 8 + g) * 36 + pb + t + 4];
                mma_bf16(s[nt], ah, bh0, bh1);
                mma_bf16(s[nt], ah, bl0, bl1);
                mma_bf16(s[nt], al, bh0, bh1);
            }
        }

        if (k0 + 63 > q0 + wm) {
            const int row0 = q0 + wm + g, row1 = row0 + 8;
#pragma unroll
            for (int nt = 0; nt < 8; nt++) {
                int c0 = k0 + nt * 8 + 2 * t, c1 = c0 + 1;
                if (c0 > row0) s[nt][0] = -1e30f;
                if (c1 > row0) s[nt][1] = -1e30f;
                if (c0 > row1) s[nt][2] = -1e30f;
                if (c1 > row1) s[nt][3] = -1e30f;
            }
        }

        float m0 = -1e30f, m1 = -1e30f;
#pragma unroll
        for (int nt = 0; nt < 8; nt++) {
            m0 = fmaxf(m0, fmaxf(s[nt][0], s[nt][1]));
            m1 = fmaxf(m1, fmaxf(s[nt][2], s[nt][3]));
        }
        m0 = fmaxf(m0, __shfl_xor_sync(0xffffffffu, m0, 1));
        m0 = fmaxf(m0, __shfl_xor_sync(0xffffffffu, m0, 2));
        m1 = fmaxf(m1, __shfl_xor_sync(0xffffffffu, m1, 1));
        m1 = fmaxf(m1, __shfl_xor_sync(0xffffffffu, m1, 2));
        float nm0 = fmaxf(rm0, m0), nm1 = fmaxf(rm1, m1);
        float al0 = __expf(rm0 - nm0), al1 = __expf(rm1 - nm1);
        rm0 = nm0; rm1 = nm1;

        float ls0 = 0.f, ls1 = 0.f;
#pragma unroll
        for (int nt = 0; nt < 8; nt++) {
            float p00 = __expf(s[nt][0] - nm0);
            float p01 = __expf(s[nt][1] - nm0);
            float p10 = __expf(s[nt][2] - nm1);
            float p11 = __expf(s[nt][3] - nm1);
            ls0 += p00 + p01;
            ls1 += p10 + p11;
            unsigned hi, lo;
            split_bf2(p00, p01, hi, lo);
            Ph[(wm + g) * 36 + 4 * nt + t] = hi;
            Pl[(wm + g) * 36 + 4 * nt + t] = lo;
            split_bf2(p10, p11, hi, lo);
            Ph[(wm + g + 8) * 36 + 4 * nt + t] = hi;
            Pl[(wm + g + 8) * 36 + 4 * nt + t] = lo;
        }
        ls0 += __shfl_xor_sync(0xffffffffu, ls0, 1);
        ls0 += __shfl_xor_sync(0xffffffffu, ls0, 2);
        ls1 += __shfl_xor_sync(0xffffffffu, ls1, 1);
        ls1 += __shfl_xor_sync(0xffffffffu, ls1, 2);
        rl0 = rl0 * al0 + ls0;
        rl1 = rl1 * al1 + ls1;

#pragma unroll
        for (int nt = 0; nt < 8; nt++) {
            accO[nt][0] *= al0; accO[nt][1] *= al0;
            accO[nt][2] *= al1; accO[nt][3] *= al1;
        }
        __syncwarp();

#pragma unroll
        for (int ksp = 0; ksp < 4; ksp++) {
            const int pb = ksp * 8;
            unsigned ah[4], al[4];
            ah[0] = Ph[(wm + g) * 36 + pb + t];
            ah[1] = Ph[(wm + g + 8) * 36 + pb + t];
            ah[2] = Ph[(wm + g) * 36 + pb + t + 4];
            ah[3] = Ph[(wm + g + 8) * 36 + pb + t + 4];
            al[0] = Pl[(wm + g) * 36 + pb + t];
            al[1] = Pl[(wm + g + 8) * 36 + pb + t];
            al[2] = Pl[(wm + g) * 36 + pb + t + 4];
            al[3] = Pl[(wm + g + 8) * 36 + pb + t + 4];
#pragma unroll
            for (int nt = 0; nt < 8; nt++) {
                unsigned bh0 = Vh[(pb + t) * 72 + nt * 8 + g];
                unsigned bh1 = Vh[(pb + t + 4) * 72 + nt * 8 + g];
                unsigned bl0 = Vl[(pb + t) * 72 + nt * 8 + g];
                unsigned bl1 = Vl[(pb + t + 4) * 72 + nt * 8 + g];
                mma_bf16(accO[nt], ah, bh0, bh1);
                mma_bf16(accO[nt], ah, bl0, bl1);
                mma_bf16(accO[nt], al, bh0, bh1);
            }
        }
        __syncthreads();
    }

    const int lrow0 = wm + g, lrow1 = lrow0 + 8;
    if (seg < 0) {
        float inv0 = 1.f / rl0, inv1 = 1.f / rl1;
        const int row0 = q0 + lrow0, row1 = q0 + lrow1;
#pragma unroll
        for (int nt = 0; nt < 8; nt++) {
            const int col = h * HDIM + nt * 8 + 2 * t;
            *(float2*)&out[(size_t)row0 * (NQH * HDIM) + col] =
                make_float2(accO[nt][0] * inv0, accO[nt][1] * inv0);
            *(float2*)&out[(size_t)row1 * (NQH * HDIM) + col] =
                make_float2(accO[nt][2] * inv1, accO[nt][3] * inv1);
        }
    } else {
        const int pi = (qtile - 8) * NQH + h;
        float* po = g_po[seg][pi];
#pragma unroll
        for (int nt = 0; nt < 8; nt++) {
            const int col = nt * 8 + 2 * t;
            *(float2*)&po[lrow0 * 64 + col] = make_float2(accO[nt][0], accO[nt][1]);
            *(float2*)&po[lrow1 * 64 + col] = make_float2(accO[nt][2], accO[nt][3]);
        }
        if (t == 0) {
            g_pm[seg][pi][lrow0] = rm0;
            g_pl[seg][pi][lrow0] = rl0;
            g_pm[seg][pi][lrow1] = rm1;
            g_pl[seg][pi][lrow1] = rl1;
        }
    }
}

// ---------------- split-K combine ----------------
__global__ void attn_combine(float* __restrict__ out) {
    const int pi = blockIdx.x;              // 0..95
    const int qtile = 8 + pi / NQH, h = pi % NQH;
    const int row = threadIdx.x >> 1;       // 0..127
    const int ch = (threadIdx.x & 1) * 32;  // column half
    float m0 = g_pm[0][pi][row], m1 = g_pm[1][pi][row];
    float l0 = g_pl[0][pi][row], l1 = g_pl[1][pi][row];
    float m = fmaxf(m0, m1);
    float a0 = __expf(m0 - m), a1 = __expf(m1 - m);
    float inv = 1.f / (l0 * a0 + l1 * a1);
    a0 *= inv; a1 *= inv;
    const float* O0 = &g_po[0][pi][row * 64 + ch];
    const float* O1 = &g_po[1][pi][row * 64 + ch];
    float* dst = &out[(size_t)(qtile * 128 + row) * (NQH * HDIM) + h * HDIM + ch];
#pragma unroll
    for (int c = 0; c < 32; c += 4) {
        float4 x0 = *(const float4*)(O0 + c);
        float4 x1 = *(const float4*)(O1 + c);
        float4 o;
        o.x = x0.x * a0 + x1.x * a1;
        o.y = x0.y * a0 + x1.y * a1;
        o.z = x0.z * a0 + x1.z * a1;
        o.w = x0.w * a0 + x1.w * a1;
        *(float4*)(dst + c) = o;
    }
}

// ---------------- router ----------------
__global__ void router_kernel(const float* __restrict__ x, const float* __restrict__ wr) {
    int t = blockIdx.x;
    __shared__ float xr[HIDDIM];
    __shared__ float lg[NEXP];
    for (int i = threadIdx.x; i < HIDDIM; i += blockDim.x) xr[i] = x[(size_t)t * HIDDIM + i];
    __syncthreads();
    if (threadIdx.x < NEXP) {
        float a = 0.f;
        for (int k = 0; k < HIDDIM; k++) a += xr[k] * wr[k * NEXP + threadIdx.x];
        lg[threadIdx.x] = a;
    }
    __syncthreads();
    if (threadIdx.x == 0) {
        int i0 = 0; float l0 = lg[0];
        for (int e = 1; e < NEXP; e++) if (lg[e] > l0) { l0 = lg[e]; i0 = e; }
        int i1 = (i0 == 0) ? 1 : 0; float l1 = lg[i1];
        for (int e = 0; e < NEXP; e++) if (e != i0 && lg[e] > l1) { l1 = lg[e]; i1 = e; }
        float w0 = 1.f / (1.f + __expf(l1 - l0));
        g_eidx[2 * t] = i0; g_eidx[2 * t + 1] = i1;
        g_ew[2 * t] = w0;   g_ew[2 * t + 1] = 1.f - w0;
        atomicAdd(&g_cnt[i0], 1);
        atomicAdd(&g_cnt[i1], 1);
    }
}

__global__ void zero_cnt_kernel() { if (threadIdx.x < NEXP) g_cnt[threadIdx.x] = 0; }

__global__ void prefix_kernel() {
    if (threadIdx.x == 0) {
        int acc = 0;
        for (int e = 0; e < NEXP; e++) { g_off[e] = acc; g_cur[e] = acc; acc += g_cnt[e]; }
        g_off[NEXP] = acc;
    }
}

__global__ void scatter_kernel() {
    int t = blockIdx.x * blockDim.x + threadIdx.x;
    if (t >= SEQ) return;
    for (int j = 0; j < 2; j++) {
        int e = g_eidx[2 * t + j];
        int pos = atomicAdd(&g_cur[e], 1);
        g_rows_tok[pos] = t;
        g_rows_w[pos] = g_ew[2 * t + j];
        g_tok_row[2 * t + j] = pos;
    }
}

// ---------------- final combine ----------------
__global__ void combine_kernel(float* __restrict__ out) {
    int t = blockIdx.x;
    int r0 = g_tok_row[2 * t], r1 = g_tok_row[2 * t + 1];
    const float* hr = g_h + (size_t)t * HIDDIM;
    const float* y0 = g_yex + (size_t)r0 * HIDDIM;
    const float* y1 = g_yex + (size_t)r1 * HIDDIM;
    for (int d = threadIdx.x; d < HIDDIM; d += blockDim.x)
        out[(size_t)t * HIDDIM + d] = hr[d] + y0[d] + y1[d];
}

// ---------------- launch ----------------
extern "C" void kernel_launch(void* const* d_in, const int* in_sizes, int n_in,
                              void* d_out, int out_size) {
    const float* x    = (const float*)d_in[0];
    const float* n1w  = (const float*)d_in[1];
    const float* wqkv = (const float*)d_in[2];
    const float* wout = (const float*)d_in[3];
    const float* n2w  = (const float*)d_in[4];
    const float* wr   = (const float*)d_in[5];
    const float* wgu  = (const float*)d_in[6];
    const float* wd   = (const float*)d_in[7];
    float* out = (float*)d_out;

    void *p_xn, *p_qkv, *p_att, *p_h, *p_mi, *p_gu, *p_hid, *p_yex;
    cudaGetSymbolAddress(&p_xn, g_xn);
    cudaGetSymbolAddress(&p_qkv, g_qkv);
    cudaGetSymbolAddress(&p_att, g_att);
    cudaGetSymbolAddress(&p_h, g_h);
    cudaGetSymbolAddress(&p_mi, g_mi);
    cudaGetSymbolAddress(&p_gu, g_gu);
    cudaGetSymbolAddress(&p_hid, g_hid);
    cudaGetSymbolAddress(&p_yex, g_yex);

    const int smem_gemm = (128 * 36 + 32 * 136) * 4;   // 35840 B
    cudaFuncSetAttribute(gemm_fp16<0>, cudaFuncAttributeMaxDynamicSharedMemorySize, smem_gemm);
    cudaFuncSetAttribute(gemm_fp16<1>, cudaFuncAttributeMaxDynamicSharedMemorySize, smem_gemm);
    cudaFuncSetAttribute(gemm_fp16<2>, cudaFuncAttributeMaxDynamicSharedMemorySize, smem_gemm);
    cudaFuncSetAttribute(gemm_fp16<3>, cudaFuncAttributeMaxDynamicSharedMemorySize, smem_gemm);

    // 1. pre-attention RMSNorm
    rmsnorm_kernel<<<SEQ, 256>>>(x, n1w, (float*)p_xn);

    // 2. QKV projection (fp16 mma)
    {
        dim3 grid(QKVC / 128, SEQ / 128);
        gemm_fp16<0><<<grid, 256, smem_gemm>>>((const float*)p_xn, wqkv, nullptr, (float*)p_qkv,
                                               SEQ, QKVC, HIDDIM);
    }

    // 3. RoPE
    rope_kernel<<<SEQ, 512>>>((float*)p_qkv);

    // 4. causal flash attention (split-bf16 mma, static split-K balancing)
    {
        dim3 grid(24, NQH);
        size_t smem = (size_t)(4 * 128 * 36 + 2 * 64 * 36 + 2 * 32 * 72) * sizeof(unsigned);
        cudaFuncSetAttribute(attn_mma, cudaFuncAttributeMaxDynamicSharedMemorySize, (int)smem);
        attn_mma<<<grid, 256, smem>>>((const float*)p_qkv, (float*)p_att);
        attn_combine<<<96, 256>>>((float*)p_att);
    }

    // 5. output projection + residual (fp16 mma)
    {
        dim3 grid(HIDDIM / 128, SEQ / 128);
        gemm_fp16<1><<<grid, 256, smem_gemm>>>((const float*)p_att, wout, x, (float*)p_h,
                                               SEQ, HIDDIM, NQH * HDIM);
    }

    // 6. pre-MoE RMSNorm
    rmsnorm_kernel<<<SEQ, 256>>>((const float*)p_h, n2w, (float*)p_mi);

    // 7. routing
    zero_cnt_kernel<<<1, 32>>>();
    router_kernel<<<SEQ, 128>>>((const float*)p_mi, wr);
    prefix_kernel<<<1, 1>>>();
    scatter_kernel<<<(SEQ + 255) / 256, 256>>>();

    // 8. expert gate/up GEMM -> g_gu (fp16 mma, gathered rows)
    {
        dim3 grid((2 * FFD) / 128, NROWS / 128, NEXP);
        gemm_fp16<2><<<grid, 256, smem_gemm>>>((const float*)p_mi, wgu, nullptr, (float*)p_gu,
                                               NROWS, 2 * FFD, HIDDIM);
    }

    // 8b. SiLU(gate) * up -> g_hid
    {
        int tot = NROWS * (FFD / 4);
        silu_kernel<<<(tot + 255) / 256, 256>>>();
    }

    // 9. expert down GEMM -> g_yex (fp16 mma, combine-weight scaled)
    {
        dim3 grid(HIDDIM / 128, NROWS / 128, NEXP);
        gemm_fp16<3><<<grid, 256, smem_gemm>>>((const float*)p_hid, wd, nullptr, (float*)p_yex,
                                               NROWS, HIDDIM, FFD);
    }

    // 10. combine
    combine_kernel<<<SEQ, 256>>>(out);
}